// round 15
// baseline (speedup 1.0000x reference)
#include <cuda_runtime.h>
#include <cstdint>

#define IN_C   64
#define OUT_C  64
#define KMAX   27
#define MAX_E  2000000
#define BATCH  16
#define PADCAP (MAX_E + KMAX * BATCH + BATCH)

// weight smem layout: [k][g][c][d]; group stride padded so the per-c LDS.128
// (lanes = h*16 + gs*4 + dq) is conflict-free in each 8-lane sub-request.
#define WGS  272                 // 256 + 16 pad
#define WKS  (4 * WGS)           // 1088
#define WTOT (KMAX * WKS)        // 29376 floats = 117504 B

// per-warp x staging: 16 rows, stride 68 floats (272B — MUST be 16B-multiple
// for float4 LDS/STS; 66 trapped with misaligned address). Store sub-requests
// are 128B contiguous; read sub-requests hit two distinct bank groups.
#define XSTR   68
#define XWARP  (16 * XSTR)       // 1088 floats = 4352 B per warp
#define NWARPS 16
#define SMEM_TOTAL ((WTOT + NWARPS * XWARP) * 4)   // 187136 B

// ---- scratch (device globals; no allocation allowed) ----
__device__ int g_hist[KMAX];
__device__ int g_cursor[KMAX];
__device__ int g_sorted[PADCAP];   // packed: eid | (k << 24); -1 = sentinel

// ---- f32x2 helpers (packed fp32, 2 FMA/instr) ----
__device__ __forceinline__ unsigned long long pack_dup(float x) {
    unsigned long long r; unsigned xi = __float_as_uint(x);
    asm("mov.b64 %0, {%1, %1};" : "=l"(r) : "r"(xi));
    return r;
}
__device__ __forceinline__ unsigned long long fma2(unsigned long long a,
                                                   unsigned long long b,
                                                   unsigned long long c) {
    unsigned long long d;
    asm("fma.rn.f32x2 %0, %1, %2, %3;" : "=l"(d) : "l"(a), "l"(b), "l"(c));
    return d;
}
__device__ __forceinline__ void unpack2(unsigned long long v, float& lo, float& hi) {
    asm("mov.b64 {%0, %1}, %2;" : "=f"(lo), "=f"(hi) : "l"(v));
}

// ---- 1) fused: out = bias, g_sorted = -1, block-aggregated k histogram ----
__global__ void init_all(float4* __restrict__ out, const float* __restrict__ bias,
                         const int* __restrict__ ka, int n4, int preN, int E) {
    __shared__ float4 b4[16];
    __shared__ int h[KMAX];
    if (threadIdx.x < 16) b4[threadIdx.x] = reinterpret_cast<const float4*>(bias)[threadIdx.x];
    if (threadIdx.x < KMAX) h[threadIdx.x] = 0;
    __syncthreads();
    int idx = blockIdx.x * blockDim.x + threadIdx.x;
    if (idx < n4)   out[idx] = b4[idx & 15];
    if (idx < preN) g_sorted[idx] = -1;
    if (idx < E)    atomicAdd(&h[ka[idx]], 1);
    __syncthreads();
    if (threadIdx.x < KMAX && h[threadIdx.x]) atomicAdd(&g_hist[threadIdx.x], h[threadIdx.x]);
}

// ---- 2) warp exclusive scan of BATCH-aligned bucket sizes; clears g_hist ----
__global__ void scan_k() {
    int lane = threadIdx.x;
    int v = (lane < KMAX) ? ((g_hist[lane] + BATCH - 1) & ~(BATCH - 1)) : 0;
    int s = v;
    #pragma unroll
    for (int o = 1; o < 32; o <<= 1) {
        int t = __shfl_up_sync(0xffffffffu, s, o);
        if (lane >= o) s += t;
    }
    if (lane < KMAX) {
        g_cursor[lane] = s - v;   // exclusive, aligned starts
        g_hist[lane] = 0;         // reset for next graph replay
    }
}

// ---- 3) scatter packed (eid | k<<24) into k-sorted order ----
__global__ void scatter_k(const int* __restrict__ ka, int E) {
    __shared__ int cnt[KMAX];
    __shared__ int bas[KMAX];
    int idx = blockIdx.x * blockDim.x + threadIdx.x;
    if (threadIdx.x < KMAX) cnt[threadIdx.x] = 0;
    __syncthreads();
    int kv = 0, my = 0;
    bool v = idx < E;
    if (v) { kv = ka[idx]; my = atomicAdd(&cnt[kv], 1); }
    __syncthreads();
    if (threadIdx.x < KMAX && cnt[threadIdx.x])
        bas[threadIdx.x] = atomicAdd(&g_cursor[threadIdx.x], cnt[threadIdx.x]);
    __syncthreads();
    if (v) g_sorted[bas[kv] + my] = idx | (kv << 24);
}

// ---- 4) fused conv: coalesced SMEM staging of x (kills 4x dq-redundant wf) ----
// Warp batch = 16 edges (k-uniform). Stage: 8 coalesced LDG.128 bring all 16
// rows (256B each) into the warp's smem buffer = 32 L1tex wavefronts/batch
// (was 128 with direct dq-redundant gathers). Read back via broadcast LDS.128
// (each 8-lane sub-request: 2 distinct 16B, 4-lane broadcast).
__global__ __launch_bounds__(512, 1) void conv_k(
    const float* __restrict__ x, const int* __restrict__ ia,
    const int* __restrict__ ja,
    const float* __restrict__ wgt, float* __restrict__ out, int nB)
{
    extern __shared__ float smem[];
    float* sw = smem;

    // cooperative weight load: src coalesced, dst scattered (once per CTA)
    for (int idx = threadIdx.x; idx < IN_C * (OUT_C / 4) * KMAX; idx += blockDim.x) {
        int k = idx % KMAX;
        int r = idx / KMAX;          // r = (g*16+c)*16 + d
        int d = r & 15;
        int c = (r >> 4) & 15;
        int g = r >> 8;
        sw[k * WKS + g * WGS + c * 16 + d] = wgt[idx];
    }
    __syncthreads();

    int lane = threadIdx.x & 31;
    int warp = threadIdx.x >> 5;
    int dq = lane & 3;
    int gs = (lane >> 2) & 3;
    int h  = lane >> 4;
    float* sxw = smem + WTOT + warp * XWARP;

    int nw = gridDim.x * (blockDim.x >> 5);

    #pragma unroll 1
    for (int b = blockIdx.x * (blockDim.x >> 5) + warp; b < nB; b += nw) {
        int base = b * BATCH;

        // lanes 0..15 hold packed edge (base+lane) metadata
        int pk = -1;
        if (lane < BATCH) pk = g_sorted[base + lane];
        int p0 = __shfl_sync(0xffffffffu, pk, 0);
        int kb = (p0 < 0) ? 0 : (p0 >> 24);        // batch-uniform k (0 for dead tail)

        int jj = 0, ii = 0;                         // jj=0 for invalid -> row 0 safe
        if (pk >= 0) {
            int eid = pk & 0x00FFFFFF;
            jj = ja[eid];
            ii = ia[eid];
        }

        // ---- stage 16 rows coalescedly: 8 LDG.128 + 8 STS.128 ----
        int f4 = lane & 15;
        int hr = lane >> 4;
        #pragma unroll
        for (int it = 0; it < 8; it++) {
            int row  = it * 2 + hr;
            int jrow = __shfl_sync(0xffffffffu, jj, row);
            float4 v = *(const float4*)(x + (size_t)jrow * IN_C + f4 * 4);
            *(float4*)(sxw + row * XSTR + f4 * 4) = v;
        }
        __syncwarp();

        // validity mask for this lane's 8 edges (half h)
        unsigned vm = 0;
        #pragma unroll
        for (int es = 0; es < 8; es++) {
            int ev = __shfl_sync(0xffffffffu, pk, h * 8 + es);
            if (ev >= 0) vm |= (1u << es);
        }

        const float* wp = sw + kb * WKS + gs * WGS + dq * 4;
        const float* xb = sxw + h * 8 * XSTR + gs * 16;

        ulonglong2 acc[8];
        #pragma unroll
        for (int es = 0; es < 8; es++) { acc[es].x = 0ull; acc[es].y = 0ull; }

        #pragma unroll
        for (int cq = 0; cq < 4; cq++) {
            // broadcast LDS: 4 dq-lanes share each 16B chunk (cheap in smem)
            float4 xq[8];
            #pragma unroll
            for (int es = 0; es < 8; es++)
                xq[es] = *(const float4*)(xb + es * XSTR + cq * 4);

            #pragma unroll
            for (int cc = 0; cc < 4; cc++) {
                int c = cq * 4 + cc;
                ulonglong2 wv = *(const ulonglong2*)(wp + c * 16);  // 1 LDS.128 / warp / c
                #pragma unroll
                for (int es = 0; es < 8; es++) {
                    float xs = (cc == 0) ? xq[es].x : (cc == 1) ? xq[es].y
                             : (cc == 2) ? xq[es].z : xq[es].w;
                    unsigned long long xd = pack_dup(xs);
                    acc[es].x = fma2(xd, wv.x, acc[es].x);
                    acc[es].y = fma2(xd, wv.y, acc[es].y);
                }
            }
        }

        // epilogue: one RED.128 per (lane, edge-slot); 2 edges per warp instr
        #pragma unroll
        for (int es = 0; es < 8; es++) {
            int ie = __shfl_sync(0xffffffffu, ii, h * 8 + es);
            if (vm & (1u << es)) {
                float a0, a1, a2, a3;
                unpack2(acc[es].x, a0, a1);
                unpack2(acc[es].y, a2, a3);
                atomicAdd(reinterpret_cast<float4*>(out + (size_t)ie * OUT_C + gs * 16 + dq * 4),
                          make_float4(a0, a1, a2, a3));
            }
        }
        __syncwarp();   // buffer reusable next iteration
    }
}

extern "C" void kernel_launch(void* const* d_in, const int* in_sizes, int n_in,
                              void* d_out, int out_size) {
    const float* x    = (const float*)d_in[0];
    const int*   ia   = (const int*)d_in[1];
    const int*   ja   = (const int*)d_in[2];
    const int*   ka   = (const int*)d_in[3];
    // d_in[4] = n (scalar), unused: derive from sizes
    const float* wgt  = (const float*)d_in[5];
    const float* bias = (const float*)d_in[6];
    float*       out  = (float*)d_out;

    int n = in_sizes[0] / IN_C;
    int E = in_sizes[1];
    if (E > MAX_E) E = MAX_E;

    int n4   = n * (OUT_C / 4);
    int preN = E + KMAX * BATCH;                 // sentinel prefill range
    int nB   = (preN + BATCH - 1) / BATCH;
    if (nB * BATCH > preN) preN = nB * BATCH;

    int initN = (n4 > preN) ? n4 : preN;
    if (E > initN) initN = E;
    init_all<<<(initN + 255) / 256, 256>>>((float4*)out, bias, ka, n4, preN, E);
    scan_k<<<1, 32>>>();
    scatter_k<<<(E + 255) / 256, 256>>>(ka, E);

    cudaFuncSetAttribute(conv_k, cudaFuncAttributeMaxDynamicSharedMemorySize,
                         SMEM_TOTAL);
    conv_k<<<148, 512, SMEM_TOTAL>>>(x, ia, ja, wgt, out, nB);
}

// round 17
// speedup vs baseline: 1.0480x; 1.0480x over previous
#include <cuda_runtime.h>
#include <cstdint>

#define IN_C   64
#define OUT_C  64
#define KMAX   27
#define MAX_E  2000000
#define BATCH  16
#define PADCAP (MAX_E + KMAX * BATCH + BATCH)

// weight smem layout: [k][c][g][d] (reload-only path; off the hot loop)
#define WKS  1024                 // floats per k
#define WTOT (KMAX * WKS)         // 27648 floats = 110592 B

// ---- scratch (device globals; no allocation allowed) ----
__device__ int g_hist[KMAX];
__device__ int g_cursor[KMAX];
__device__ int g_sorted[PADCAP];   // packed: eid | (k << 24); -1 = sentinel

// ---- f32x2 helpers (packed fp32, 2 FMA/instr) ----
__device__ __forceinline__ unsigned long long pack_dup(float x) {
    unsigned long long r; unsigned xi = __float_as_uint(x);
    asm("mov.b64 %0, {%1, %1};" : "=l"(r) : "r"(xi));
    return r;
}
__device__ __forceinline__ unsigned long long fma2(unsigned long long a,
                                                   unsigned long long b,
                                                   unsigned long long c) {
    unsigned long long d;
    asm("fma.rn.f32x2 %0, %1, %2, %3;" : "=l"(d) : "l"(a), "l"(b), "l"(c));
    return d;
}
__device__ __forceinline__ void unpack2(unsigned long long v, float& lo, float& hi) {
    asm("mov.b64 {%0, %1}, %2;" : "=f"(lo), "=f"(hi) : "l"(v));
}
// vector reduction: one RED.64 adds both of this lane's output channels
__device__ __forceinline__ void red_v2(float* p, float a, float b) {
    asm volatile("red.global.add.v2.f32 [%0], {%1, %2};"
                 :: "l"(p), "f"(a), "f"(b) : "memory");
}

// ---- 1) fused: out = bias, g_sorted = -1, block-aggregated k histogram ----
__global__ void init_all(float4* __restrict__ out, const float* __restrict__ bias,
                         const int* __restrict__ ka, int n4, int preN, int E) {
    __shared__ float4 b4[16];
    __shared__ int h[KMAX];
    if (threadIdx.x < 16) b4[threadIdx.x] = reinterpret_cast<const float4*>(bias)[threadIdx.x];
    if (threadIdx.x < KMAX) h[threadIdx.x] = 0;
    __syncthreads();
    int idx = blockIdx.x * blockDim.x + threadIdx.x;
    if (idx < n4)   out[idx] = b4[idx & 15];
    if (idx < preN) g_sorted[idx] = -1;
    if (idx < E)    atomicAdd(&h[ka[idx]], 1);
    __syncthreads();
    if (threadIdx.x < KMAX && h[threadIdx.x]) atomicAdd(&g_hist[threadIdx.x], h[threadIdx.x]);
}

// ---- 2) warp exclusive scan of BATCH-aligned bucket sizes; clears g_hist ----
__global__ void scan_k() {
    int lane = threadIdx.x;
    int v = (lane < KMAX) ? ((g_hist[lane] + BATCH - 1) & ~(BATCH - 1)) : 0;
    int s = v;
    #pragma unroll
    for (int o = 1; o < 32; o <<= 1) {
        int t = __shfl_up_sync(0xffffffffu, s, o);
        if (lane >= o) s += t;
    }
    if (lane < KMAX) {
        g_cursor[lane] = s - v;   // exclusive, aligned starts
        g_hist[lane] = 0;         // reset for next graph replay
    }
}

// ---- 3) scatter packed (eid | k<<24) into k-sorted order ----
__global__ void scatter_k(const int* __restrict__ ka, int E) {
    __shared__ int cnt[KMAX];
    __shared__ int bas[KMAX];
    int idx = blockIdx.x * blockDim.x + threadIdx.x;
    if (threadIdx.x < KMAX) cnt[threadIdx.x] = 0;
    __syncthreads();
    int kv = 0, my = 0;
    bool v = idx < E;
    if (v) { kv = ka[idx]; my = atomicAdd(&cnt[kv], 1); }
    __syncthreads();
    if (threadIdx.x < KMAX && cnt[threadIdx.x])
        bas[threadIdx.x] = atomicAdd(&g_cursor[threadIdx.x], cnt[threadIdx.x]);
    __syncthreads();
    if (v) g_sorted[bas[kv] + my] = idx | (kv << 24);
}

// ---- 4) fused conv: weights-in-registers, lane = (gs, d8) ----
// Lane owns output channels [gs*16 + d8*2, +1] for ALL 16 edges of the batch.
// Weight set per lane = 16 f32x2 regs, reloaded only when the bucket k changes
// (warps own CONTIGUOUS batch ranges -> ~1-2 reloads per warp total).
// Hot-loop L1tex work/batch: 128 x-wf + 16 RED + meta (weight LDS eliminated).
__global__ __launch_bounds__(512, 1) void conv_k(
    const float* __restrict__ x, const int* __restrict__ ia,
    const int* __restrict__ ja,
    const float* __restrict__ wgt, float* __restrict__ out, int nB)
{
    extern __shared__ float sw[];

    // cooperative weight load: src coalesced; dst = k*1024 + c*64 + g*16 + d
    for (int idx = threadIdx.x; idx < WTOT; idx += blockDim.x) {
        int k = idx % KMAX;
        int r = idx / KMAX;          // r = (g*16+c)*16 + d
        int d = r & 15;
        int c = (r >> 4) & 15;
        int g = r >> 8;
        sw[k * WKS + c * 64 + g * 16 + d] = wgt[idx];
    }
    __syncthreads();

    int lane = threadIdx.x & 31;
    int warp = threadIdx.x >> 5;
    int gs = lane >> 3;          // group 0..3
    int d8 = lane & 7;           // d-pair 0..7 (channels d8*2, d8*2+1)

    // contiguous batch range per warp (keeps k constant within a warp's walk)
    int gw  = blockIdx.x * (blockDim.x >> 5) + warp;
    int nwt = gridDim.x * (blockDim.x >> 5);
    int chunk = (nB + nwt - 1) / nwt;
    int b0 = gw * chunk;
    int b1 = b0 + chunk; if (b1 > nB) b1 = nB;

    unsigned long long w2[16];   // this lane's weights for current k
    int cur_k = -1;

    #pragma unroll 1
    for (int b = b0; b < b1; b++) {
        int base = b * BATCH;

        int pk = -1;
        if (lane < BATCH) pk = g_sorted[base + lane];
        int p0 = __shfl_sync(0xffffffffu, pk, 0);
        if (p0 < 0) continue;                       // wholly-empty padding batch
        int kb = p0 >> 24;
        unsigned vm = __ballot_sync(0xffffffffu, pk >= 0);  // bits 0..15 valid

        int jj = 0, ii = 0;
        if (pk >= 0) {
            int eid = pk & 0x00FFFFFF;
            jj = ja[eid];
            ii = ia[eid];
        }

        if (kb != cur_k) {                          // rare: bucket boundary
            cur_k = kb;
            const float* wb = sw + kb * WKS + gs * 16 + d8 * 2;
            #pragma unroll
            for (int c = 0; c < 16; c++)
                w2[c] = *(const unsigned long long*)(wb + c * 64);
        }

        unsigned long long acc[16];
        #pragma unroll
        for (int es = 0; es < 16; es++) acc[es] = 0ull;

        // row-pairs: 8 LDG.128 in flight, then 32 FMA2 per pair
        #pragma unroll
        for (int p = 0; p < 8; p++) {
            int r0 = __shfl_sync(0xffffffffu, jj, 2 * p);
            int r1 = __shfl_sync(0xffffffffu, jj, 2 * p + 1);
            const float* x0 = x + (size_t)r0 * IN_C + gs * 16;
            const float* x1 = x + (size_t)r1 * IN_C + gs * 16;
            float4 a0 = *(const float4*)(x0);
            float4 a1 = *(const float4*)(x0 + 4);
            float4 a2 = *(const float4*)(x0 + 8);
            float4 a3 = *(const float4*)(x0 + 12);
            float4 c0 = *(const float4*)(x1);
            float4 c1 = *(const float4*)(x1 + 4);
            float4 c2 = *(const float4*)(x1 + 8);
            float4 c3 = *(const float4*)(x1 + 12);

            const float xs0[16] = {a0.x,a0.y,a0.z,a0.w, a1.x,a1.y,a1.z,a1.w,
                                   a2.x,a2.y,a2.z,a2.w, a3.x,a3.y,a3.z,a3.w};
            const float xs1[16] = {c0.x,c0.y,c0.z,c0.w, c1.x,c1.y,c1.z,c1.w,
                                   c2.x,c2.y,c2.z,c2.w, c3.x,c3.y,c3.z,c3.w};
            #pragma unroll
            for (int c = 0; c < 16; c++) {
                acc[2 * p]     = fma2(pack_dup(xs0[c]), w2[c], acc[2 * p]);
                acc[2 * p + 1] = fma2(pack_dup(xs1[c]), w2[c], acc[2 * p + 1]);
            }
        }

        // epilogue: one RED.64 (v2.f32) per (lane, edge)
        #pragma unroll
        for (int es = 0; es < 16; es++) {
            int ie = __shfl_sync(0xffffffffu, ii, es);
            if (vm & (1u << es)) {
                float lo, hi;
                unpack2(acc[es], lo, hi);
                red_v2(out + (size_t)ie * OUT_C + gs * 16 + d8 * 2, lo, hi);
            }
        }
    }
}

extern "C" void kernel_launch(void* const* d_in, const int* in_sizes, int n_in,
                              void* d_out, int out_size) {
    const float* x    = (const float*)d_in[0];
    const int*   ia   = (const int*)d_in[1];
    const int*   ja   = (const int*)d_in[2];
    const int*   ka   = (const int*)d_in[3];
    // d_in[4] = n (scalar), unused: derive from sizes
    const float* wgt  = (const float*)d_in[5];
    const float* bias = (const float*)d_in[6];
    float*       out  = (float*)d_out;

    int n = in_sizes[0] / IN_C;
    int E = in_sizes[1];
    if (E > MAX_E) E = MAX_E;

    int n4   = n * (OUT_C / 4);
    int preN = E + KMAX * BATCH;                 // sentinel prefill range
    int nB   = (preN + BATCH - 1) / BATCH;
    if (nB * BATCH > preN) preN = nB * BATCH;

    int initN = (n4 > preN) ? n4 : preN;
    if (E > initN) initN = E;
    init_all<<<(initN + 255) / 256, 256>>>((float4*)out, bias, ka, n4, preN, E);
    scan_k<<<1, 32>>>();
    scatter_k<<<(E + 255) / 256, 256>>>(ka, E);

    cudaFuncSetAttribute(conv_k, cudaFuncAttributeMaxDynamicSharedMemorySize,
                         WTOT * 4);
    conv_k<<<148, 512, WTOT * 4>>>(x, ia, ja, wgt, out, nB);
}